// round 4
// baseline (speedup 1.0000x reference)
#include <cuda_runtime.h>

#define P_ 2
#define B_ 96
#define A_ 32
#define N_ 3072        // B_*A_
#define NT_ 24
#define MD_ 4
#define MA_ 4
#define NPOL_ 8
#define CH_ 6          // j-range chunks per (pose,block)
#define TPB_ 256
#define JPT_ ((N_/CH_)/TPB_)   // 2 atoms per thread
#define C_LK 0.0897935610625833f
#define FULLM 0xffffffffu

// Scratch (no allocations allowed)
__device__ double g_partial[P_*B_*CH_*2];
__device__ unsigned int g_done;   // zero-init; last CTA resets -> graph-replay safe

__device__ __forceinline__ int clampA(int v){ return min(max(v,0), A_-1); }

__global__ void __launch_bounds__(TPB_) lkball_kernel(
    const float* __restrict__ coords,
    const int*   __restrict__ btype,
    const int*   __restrict__ minsep,
    const int*   __restrict__ bonds,     // (NT,A,2)
    const int*   __restrict__ ranges,    // (NT,A,2)
    const int*   __restrict__ n_donH,
    const int*   __restrict__ n_acc,
    const int*   __restrict__ donH_i,
    const int*   __restrict__ don_hvy_i,
    const int*   __restrict__ acc_i_arr,
    const int*   __restrict__ hyb_arr,
    const float* __restrict__ lkp,       // (NT,A,4) -> float4 aligned
    const int*   __restrict__ is_h,      // (NT,A)
    const int*   __restrict__ pathd,     // (NT,A,A)
    const float* __restrict__ lkgp,
    const float* __restrict__ wgp,
    const float* __restrict__ sp2t,
    const float* __restrict__ sp3t,
    const float* __restrict__ ringt,
    float*       __restrict__ out)
{
    __shared__ float4 st_pol[NPOL_], st_w0[NPOL_], st_w1[NPOL_];
    __shared__ int    st_a[NPOL_], st_act[NPOL_];
    __shared__ float4 s_pol[NPOL_], s_w0[NPOL_], s_w1[NPOL_];
    __shared__ int    s_arow[NPOL_];
    __shared__ unsigned char s_sepok[B_];
    __shared__ short  s_bt[B_];
    __shared__ unsigned s_hmask[NT_];    // bit a set => atom a is hydrogen
    __shared__ double s_red[TPB_/32][2];

    int cta = blockIdx.x;
    int c   = cta % CH_;
    int pb  = cta / CH_;
    int p   = pb / B_;
    int b   = pb - p*B_;
    int tid = threadIdx.x;
    int bt  = btype[p*B_+b];
    const float* cblk = coords + (size_t)(p*N_ + b*A_)*3;
    const float4* lkp4 = (const float4*)lkp;

    // ---- water generation for the 8 polar slots (threads 0..7) ----
    if (tid < NPOL_) {
        float wdist = wgp[0], wang = wgp[1];
        int active = 0, ai = 0;
        float xp0=0,xp1=0,xp2=0,w00=0,w01=0,w02=0,w10=0,w11=0,w12=0;
        if (tid < MD_) {                       // donor slot
            int i = tid;
            if (i < n_donH[bt]) {
                active = 1;
                ai      = clampA(don_hvy_i[bt*MD_+i]);
                int hi  = clampA(donH_i[bt*MD_+i]);
                float hx=cblk[ai*3], hy=cblk[ai*3+1], hz=cblk[ai*3+2];
                float Hx=cblk[hi*3], Hy=cblk[hi*3+1], Hz=cblk[hi*3+2];
                float dx=Hx-hx, dy=Hy-hy, dz=Hz-hz;
                float inv = rsqrtf(dx*dx+dy*dy+dz*dz + 1e-12f);
                xp0=hx; xp1=hy; xp2=hz;
                w00=hx+wdist*inv*dx; w01=hy+wdist*inv*dy; w02=hz+wdist*inv*dz;
                w10=1e5f; w11=1e5f; w12=1e5f;      // masked water -> far sentinel
            }
        } else {                               // acceptor slot
            int i = tid - MD_;
            if (i < n_acc[bt]) {
                active = 1;
                ai        = clampA(acc_i_arr[bt*MA_+i]);
                int r0    = clampA(ranges[(bt*A_+ai)*2]);
                int base  = clampA(bonds [(bt*A_+r0)*2+1]);
                int r1    = clampA(ranges[(bt*A_+base)*2]);
                int base2 = clampA(bonds [(bt*A_+r1)*2+1]);
                float cx=cblk[ai*3],   cy=cblk[ai*3+1],   cz=cblk[ai*3+2];
                float bx=cblk[base*3], by=cblk[base*3+1], bz=cblk[base*3+2];
                float ax=cblk[base2*3],ay=cblk[base2*3+1],az=cblk[base2*3+2];
                float e1x=cx-bx, e1y=cy-by, e1z=cz-bz;
                float inv = rsqrtf(e1x*e1x+e1y*e1y+e1z*e1z + 1e-12f);
                e1x*=inv; e1y*=inv; e1z*=inv;
                float ux=bx-ax, uy=by-ay, uz=bz-az;
                float nx=uy*e1z-uz*e1y, ny=uz*e1x-ux*e1z, nz=ux*e1y-uy*e1x;
                inv = rsqrtf(nx*nx+ny*ny+nz*nz + 1e-12f);
                nx*=inv; ny*=inv; nz*=inv;
                float e2x=ny*e1z-nz*e1y, e2y=nz*e1x-nx*e1z, e2z=nx*e1y-ny*e1x;
                int hyb = hyb_arr[bt*MA_+i];
                float chi0, chi1;
                if      (hyb == 0) { chi0=sp2t[0];  chi1=sp2t[1];  }
                else if (hyb == 1) { chi0=sp3t[0];  chi1=sp3t[1];  }
                else               { chi0=ringt[0]; chi1=ringt[1]; }
                float ct=cosf(wang), st=sinf(wang);
                float a1 = -wdist*ct;
                float b0 = wdist*st*cosf(chi0), c0 = wdist*st*sinf(chi0);
                float b1 = wdist*st*cosf(chi1), c1 = wdist*st*sinf(chi1);
                xp0=cx; xp1=cy; xp2=cz;
                w00 = cx + a1*e1x + b0*e2x + c0*nx;
                w01 = cy + a1*e1y + b0*e2y + c0*ny;
                w02 = cz + a1*e1z + b0*e2z + c0*nz;
                w10 = cx + a1*e1x + b1*e2x + c1*nx;
                w11 = cy + a1*e1y + b1*e2y + c1*ny;
                w12 = cz + a1*e1z + b1*e2z + c1*nz;
            }
        }
        st_act[tid] = active;
        if (active) {
            float4 q = lkp4[bt*A_+ai];           // ri,dgi,lam,vol
            st_pol[tid] = make_float4(xp0, xp1, xp2, q.x);
            st_w0[tid]  = make_float4(w00, w01, w02, C_LK*q.y/q.z);
            st_w1[tid]  = make_float4(w10, w11, w12, 1.0f/q.z);
            st_a[tid]   = ai*A_;
        }
    }
    // inter-block sep mask + block types for this pose
    if (tid < B_) {
        s_sepok[tid] = (minsep[(p*B_+b)*B_+tid] >= 4) ? 1 : 0;
        s_bt[tid]    = (short)btype[p*B_+tid];
    }
    // per-block-type hydrogen bitmask
    if (tid >= 128 && tid < 128+NT_) {
        int t = tid - 128;
        unsigned m = 0;
        for (int a = 0; a < A_; a++) m |= (is_h[t*A_+a] != 0) ? (1u<<a) : 0u;
        s_hmask[t] = m;
    }
    __syncthreads();
    if (tid == 0) {                         // compact + pad to 8 with dummies
        int n = 0;
        for (int t = 0; t < NPOL_; t++) if (st_act[t]) {
            s_pol[n]=st_pol[t]; s_w0[n]=st_w0[t]; s_w1[n]=st_w1[t]; s_arow[n]=st_a[t];
            n++;
        }
        for (; n < NPOL_; n++) {
            s_pol[n]=make_float4(1e6f,1e6f,1e6f,0.f);   // never passes cutoff
            s_w0[n]=make_float4(0,0,0,0); s_w1[n]=make_float4(0,0,0,1.f);
            s_arow[n]=0;
        }
    }
    __syncthreads();

    // hoist the 8 polar positions into registers
    float px[NPOL_], py[NPOL_], pz[NPOL_];
    #pragma unroll
    for (int k = 0; k < NPOL_; k++) {
        float4 q = s_pol[k];
        px[k]=q.x; py[k]=q.y; pz[k]=q.z;
    }

    float cutoff2 = lkgp[0]*lkgp[0];
    float ramp2   = lkgp[1];
    float d2lr    = lkgp[2] + ramp2;
    float invramp = 1.0f/ramp2;

    const float* cp   = coords + (size_t)p*N_*3;
    const int*   prow = pathd + bt*A_*A_;
    int lane = tid & 31;

    float sum0 = 0.f, sum1 = 0.f;
    int jbase = c*(N_/CH_) + tid;
    #pragma unroll
    for (int it = 0; it < JPT_; it++) {
        int j = jbase + it*TPB_;
        float ax = cp[3*j], ay = cp[3*j+1], az = cp[3*j+2];
        int  bj  = j >> 5;
        int  ajA = j & 31;
        bool heavy = ((s_hmask[s_bt[bj]] >> ajA) & 1u) == 0u;

        unsigned m[NPOL_];
        int total = 0;
        #pragma unroll
        for (int k = 0; k < NPOL_; k++) {
            float dx = px[k]-ax, dy = py[k]-ay, dz = pz[k]-az;
            float d2 = dx*dx + dy*dy + dz*dz;
            m[k] = __ballot_sync(FULLM, (d2 < cutoff2) && heavy);
            total += __popc(m[k]);
        }
        if (total == 0) continue;           // warp-uniform (ballot-derived)

        for (int base = 0; base < total; base += 32) {
            int t = base + lane;
            // select pair t: (selk, off-th set bit of m[selk])
            int off = t; unsigned selmask = 0; int selk = NPOL_;
            #pragma unroll
            for (int kk = 0; kk < NPOL_; kk++) {
                int cc = __popc(m[kk]);
                if (selk == NPOL_) {
                    if (off < cc) { selmask = m[kk]; selk = kk; }
                    else off -= cc;
                }
            }
            bool valid = (selk < NPOL_);
            int nth = valid ? min(off, 31) : 0;
            int src = valid ? (int)__fns(selmask, 0, nth+1) : 0;
            // gather source atom data (warp-uniform shfl participation)
            float sax = __shfl_sync(FULLM, ax, src);
            float say = __shfl_sync(FULLM, ay, src);
            float saz = __shfl_sync(FULLM, az, src);
            int  srcj = (j - lane) + src;
            int  sbj  = srcj >> 5;
            int  sajA = srcj & 31;
            if (valid) {
                bool same = (sbj == b);
                bool ok = same ? (prow[s_arow[selk]+sajA] >= 4)
                               : (s_sepok[sbj] != 0);
                if (ok) {
                    int   btj = s_bt[sbj];
                    float4 q  = lkp4[btj*A_+sajA];      // rj=q.x, vol=q.w
                    float4 pol = s_pol[selk];
                    float4 w0  = s_w0[selk];
                    float4 w1  = s_w1[selk];
                    float dx = pol.x-sax, dy = pol.y-say, dz = pol.z-saz;
                    float d2c = fmaxf(dx*dx + dy*dy + dz*dz, 0.01f);
                    float d   = sqrtf(d2c);
                    float xq  = (d - pol.w - q.x) * w1.w;
                    float lk  = __fdividef(w0.w * q.w * __expf(-xq*xq), d2c);
                    float a0x=w0.x-sax, a0y=w0.y-say, a0z=w0.z-saz;
                    float dw0 = a0x*a0x + a0y*a0y + a0z*a0z;
                    float a1x=w1.x-sax, a1y=w1.y-say, a1z=w1.z-saz;
                    float dw1 = a1x*a1x + a1y*a1y + a1z*a1z;
                    float dm = fminf(dw0, dw1);
                    float wt = __saturatef((d2lr - dm) * invramp);
                    float fr = wt*wt*(3.f - 2.f*wt);
                    sum0 += lk;
                    sum1 += lk*fr;
                }
            }
        }
    }

    // deterministic CTA reduction (fp64)
    double d0 = sum0, d1 = sum1;
    for (int off = 16; off; off >>= 1) {
        d0 += __shfl_xor_sync(FULLM, d0, off);
        d1 += __shfl_xor_sync(FULLM, d1, off);
    }
    int warp = tid >> 5;
    if (lane == 0) { s_red[warp][0]=d0; s_red[warp][1]=d1; }
    __syncthreads();
    if (tid == 0) {
        double a=0, cc=0;
        #pragma unroll
        for (int w = 0; w < TPB_/32; w++) { a+=s_red[w][0]; cc+=s_red[w][1]; }
        g_partial[cta*2]   = a;
        g_partial[cta*2+1] = cc;
    }

    // ---- last-CTA final reduce (fixed-order -> deterministic) ----
    __shared__ bool s_last;
    __threadfence();
    if (tid == 0)
        s_last = (atomicAdd(&g_done, 1u) == (unsigned)(gridDim.x - 1));
    __syncthreads();
    if (!s_last) return;

    __shared__ double rr0[TPB_], rr1[TPB_];
    for (int pp = 0; pp < P_; pp++) {
        double a = 0, cc = 0;
        for (int i = tid; i < B_*CH_; i += TPB_) {
            a  += g_partial[(pp*B_*CH_+i)*2];
            cc += g_partial[(pp*B_*CH_+i)*2+1];
        }
        rr0[tid] = a; rr1[tid] = cc;
        __syncthreads();
        for (int s = TPB_/2; s >= 1; s >>= 1) {
            if (tid < s) { rr0[tid] += rr0[tid+s]; rr1[tid] += rr1[tid+s]; }
            __syncthreads();
        }
        if (tid == 0) {
            out[pp]     = (float)rr0[0];
            out[P_+pp]  = (float)rr1[0];
        }
        __syncthreads();
    }
    if (tid == 0) g_done = 0;            // reset for next graph replay
}

extern "C" void kernel_launch(void* const* d_in, const int* in_sizes, int n_in,
                              void* d_out, int out_size) {
    const float* coords  = (const float*)d_in[0];
    const int*   btype   = (const int*)  d_in[1];
    const int*   minsep  = (const int*)  d_in[2];
    // d_in[3] = bt_n_atoms (unused: all blocks have A_ atoms)
    const int*   bonds   = (const int*)  d_in[4];
    const int*   ranges  = (const int*)  d_in[5];
    const int*   n_donH  = (const int*)  d_in[6];
    const int*   n_acc   = (const int*)  d_in[7];
    const int*   donH_i  = (const int*)  d_in[8];
    const int*   don_hvy = (const int*)  d_in[9];
    const int*   acc_i   = (const int*)  d_in[10];
    const int*   hyb     = (const int*)  d_in[11];
    const int*   is_h    = (const int*)  d_in[12];
    const float* lkp     = (const float*)d_in[13];
    const int*   pathd   = (const int*)  d_in[14];
    const float* lkgp    = (const float*)d_in[15];
    const float* wgp     = (const float*)d_in[16];
    const float* sp2     = (const float*)d_in[17];
    const float* sp3     = (const float*)d_in[18];
    const float* ringt   = (const float*)d_in[19];

    lkball_kernel<<<P_*B_*CH_, TPB_>>>(coords, btype, minsep, bonds, ranges,
                                       n_donH, n_acc, donH_i, don_hvy, acc_i, hyb,
                                       lkp, is_h, pathd, lkgp, wgp, sp2, sp3, ringt,
                                       (float*)d_out);
}

// round 5
// speedup vs baseline: 1.0606x; 1.0606x over previous
#include <cuda_runtime.h>

#define P_ 2
#define B_ 96
#define A_ 32
#define N_ 3072        // B_*A_
#define NT_ 24
#define MD_ 4
#define MA_ 4
#define NPOL_ 8
#define CH_ 4          // j-range chunks per (pose,block)
#define TPB_ 256
#define JCHUNK_ (N_/CH_)       // 768 j atoms per CTA
#define JPT_ (JCHUNK_/TPB_)    // 3 atoms per thread
#define C_LK 0.0897935610625833f
#define FULLM 0xffffffffu

// Scratch (no allocations allowed)
__device__ double g_partial[P_*B_*CH_*2];
__device__ unsigned int g_done;   // zero-init; last CTA resets -> graph-replay safe

__device__ __forceinline__ int clampA(int v){ return min(max(v,0), A_-1); }

__global__ void __launch_bounds__(TPB_) lkball_kernel(
    const float* __restrict__ coords,
    const int*   __restrict__ btype,
    const int*   __restrict__ minsep,
    const int*   __restrict__ bonds,     // (NT,A,2)
    const int*   __restrict__ ranges,    // (NT,A,2)
    const int*   __restrict__ n_donH,
    const int*   __restrict__ n_acc,
    const int*   __restrict__ donH_i,
    const int*   __restrict__ don_hvy_i,
    const int*   __restrict__ acc_i_arr,
    const int*   __restrict__ hyb_arr,
    const float* __restrict__ lkp,       // (NT,A,4) -> float4 aligned
    const int*   __restrict__ is_h,      // (NT,A)
    const int*   __restrict__ pathd,     // (NT,A,A)
    const float* __restrict__ lkgp,
    const float* __restrict__ wgp,
    const float* __restrict__ sp2t,
    const float* __restrict__ sp3t,
    const float* __restrict__ ringt,
    float*       __restrict__ out)
{
    __shared__ float4 st_pol[NPOL_], st_w0[NPOL_], st_w1[NPOL_];
    __shared__ int    st_a[NPOL_], st_act[NPOL_];
    __shared__ float4 s_pol[NPOL_], s_w0[NPOL_], s_w1[NPOL_];
    __shared__ int    s_arow[NPOL_];
    __shared__ unsigned s_pmask[NPOL_];     // same-block sep>=4 bit per atom-in-block
    __shared__ unsigned char s_sepok[B_];
    __shared__ short  s_bt[B_];
    __shared__ float4 s_xyz[JCHUNK_];       // staged j atoms: x,y,z,rj (H -> -1e6 sentinel)
    __shared__ float  s_vol[JCHUNK_];
    __shared__ double s_red[TPB_/32][2];

    int cta = blockIdx.x;
    int c   = cta % CH_;
    int pb  = cta / CH_;
    int p   = pb / B_;
    int b   = pb - p*B_;
    int tid = threadIdx.x;
    int bt  = btype[p*B_+b];
    const float* cblk = coords + (size_t)(p*N_ + b*A_)*3;
    const float4* lkp4 = (const float4*)lkp;

    // ---- water generation for the 8 polar slots (threads 0..7) ----
    if (tid < NPOL_) {
        float wdist = wgp[0], wang = wgp[1];
        int active = 0, ai = 0;
        float xp0=0,xp1=0,xp2=0,w00=0,w01=0,w02=0,w10=0,w11=0,w12=0;
        if (tid < MD_) {                       // donor slot
            int i = tid;
            if (i < n_donH[bt]) {
                active = 1;
                ai      = clampA(don_hvy_i[bt*MD_+i]);
                int hi  = clampA(donH_i[bt*MD_+i]);
                float hx=cblk[ai*3], hy=cblk[ai*3+1], hz=cblk[ai*3+2];
                float Hx=cblk[hi*3], Hy=cblk[hi*3+1], Hz=cblk[hi*3+2];
                float dx=Hx-hx, dy=Hy-hy, dz=Hz-hz;
                float inv = rsqrtf(dx*dx+dy*dy+dz*dz + 1e-12f);
                xp0=hx; xp1=hy; xp2=hz;
                w00=hx+wdist*inv*dx; w01=hy+wdist*inv*dy; w02=hz+wdist*inv*dz;
                w10=1e5f; w11=1e5f; w12=1e5f;      // masked water -> far sentinel
            }
        } else {                               // acceptor slot
            int i = tid - MD_;
            if (i < n_acc[bt]) {
                active = 1;
                ai        = clampA(acc_i_arr[bt*MA_+i]);
                int r0    = clampA(ranges[(bt*A_+ai)*2]);
                int base  = clampA(bonds [(bt*A_+r0)*2+1]);
                int r1    = clampA(ranges[(bt*A_+base)*2]);
                int base2 = clampA(bonds [(bt*A_+r1)*2+1]);
                float cx=cblk[ai*3],   cy=cblk[ai*3+1],   cz=cblk[ai*3+2];
                float bx=cblk[base*3], by=cblk[base*3+1], bz=cblk[base*3+2];
                float ax=cblk[base2*3],ay=cblk[base2*3+1],az=cblk[base2*3+2];
                float e1x=cx-bx, e1y=cy-by, e1z=cz-bz;
                float inv = rsqrtf(e1x*e1x+e1y*e1y+e1z*e1z + 1e-12f);
                e1x*=inv; e1y*=inv; e1z*=inv;
                float ux=bx-ax, uy=by-ay, uz=bz-az;
                float nx=uy*e1z-uz*e1y, ny=uz*e1x-ux*e1z, nz=ux*e1y-uy*e1x;
                inv = rsqrtf(nx*nx+ny*ny+nz*nz + 1e-12f);
                nx*=inv; ny*=inv; nz*=inv;
                float e2x=ny*e1z-nz*e1y, e2y=nz*e1x-nx*e1z, e2z=nx*e1y-ny*e1x;
                int hyb = hyb_arr[bt*MA_+i];
                float chi0, chi1;
                if      (hyb == 0) { chi0=sp2t[0];  chi1=sp2t[1];  }
                else if (hyb == 1) { chi0=sp3t[0];  chi1=sp3t[1];  }
                else               { chi0=ringt[0]; chi1=ringt[1]; }
                float ct=cosf(wang), st=sinf(wang);
                float a1 = -wdist*ct;
                float b0 = wdist*st*cosf(chi0), c0 = wdist*st*sinf(chi0);
                float b1 = wdist*st*cosf(chi1), c1 = wdist*st*sinf(chi1);
                xp0=cx; xp1=cy; xp2=cz;
                w00 = cx + a1*e1x + b0*e2x + c0*nx;
                w01 = cy + a1*e1y + b0*e2y + c0*ny;
                w02 = cz + a1*e1z + b0*e2z + c0*nz;
                w10 = cx + a1*e1x + b1*e2x + c1*nx;
                w11 = cy + a1*e1y + b1*e2y + c1*ny;
                w12 = cz + a1*e1z + b1*e2z + c1*nz;
            }
        }
        st_act[tid] = active;
        if (active) {
            float4 q = lkp4[bt*A_+ai];           // ri,dgi,lam,vol
            st_pol[tid] = make_float4(xp0, xp1, xp2, q.x);
            st_w0[tid]  = make_float4(w00, w01, w02, C_LK*q.y/q.z);
            st_w1[tid]  = make_float4(w10, w11, w12, 1.0f/q.z);
            st_a[tid]   = ai*A_;
        }
    }
    // inter-block sep mask + block types for this pose
    if (tid < B_) {
        s_sepok[tid] = (minsep[(p*B_+b)*B_+tid] >= 4) ? 1 : 0;
        s_bt[tid]    = (short)btype[p*B_+tid];
    }
    __syncthreads();
    if (tid == 0) {                         // compact + pad to 8 with dummies
        int n = 0;
        for (int t = 0; t < NPOL_; t++) if (st_act[t]) {
            s_pol[n]=st_pol[t]; s_w0[n]=st_w0[t]; s_w1[n]=st_w1[t]; s_arow[n]=st_a[t];
            n++;
        }
        for (; n < NPOL_; n++) {
            s_pol[n]=make_float4(1e6f,1e6f,1e6f,0.f);   // never passes cutoff
            s_w0[n]=make_float4(0,0,0,0); s_w1[n]=make_float4(0,0,0,1.f);
            s_arow[n]=0;
        }
    }
    // stage this CTA's j range: coords+rj (H -> far sentinel), vol
    {
        int jbase = c*JCHUNK_;
        const float* cp = coords + (size_t)p*N_*3;
        #pragma unroll
        for (int i = tid; i < JCHUNK_; i += TPB_) {
            int j   = jbase + i;
            int bj  = j >> 5;
            int a   = j & 31;
            int btj = s_bt[bj];
            float4 q = lkp4[btj*A_+a];
            bool hyd = (is_h[btj*A_+a] != 0);
            float x = cp[3*j], y = cp[3*j+1], z = cp[3*j+2];
            s_xyz[i] = hyd ? make_float4(-1e6f,-1e6f,-1e6f,0.f)
                           : make_float4(x, y, z, q.x);
            s_vol[i] = q.w;
        }
    }
    __syncthreads();
    // same-block separation bitmasks: warp k -> pol k, lane a -> atom a
    if (tid < NPOL_*32) {
        int k = tid >> 5, a = tid & 31;
        unsigned mk = __ballot_sync(FULLM, pathd[bt*A_*A_ + s_arow[k] + a] >= 4);
        if (a == 0) s_pmask[k] = mk;
    }
    __syncthreads();

    // hoist the 8 polar positions + ri into registers
    float px[NPOL_], py[NPOL_], pz[NPOL_], pri[NPOL_];
    #pragma unroll
    for (int k = 0; k < NPOL_; k++) {
        float4 q = s_pol[k];
        px[k]=q.x; py[k]=q.y; pz[k]=q.z; pri[k]=q.w;
    }

    float cutoff2 = lkgp[0]*lkgp[0];
    float ramp2   = lkgp[1];
    float d2lr    = lkgp[2] + ramp2;
    float invramp = 1.0f/ramp2;

    int jbase = c*JCHUNK_;
    float sum0 = 0.f, sum1 = 0.f;
    #pragma unroll
    for (int it = 0; it < JPT_; it++) {
        int i = it*TPB_ + tid;               // smem index
        float4 aj = s_xyz[i];                // x,y,z,rj  (LDS.128)
        float d2[NPOL_];
        #pragma unroll
        for (int k = 0; k < NPOL_; k++) {
            float dx = px[k]-aj.x, dy = py[k]-aj.y, dz = pz[k]-aj.z;
            d2[k] = dx*dx + dy*dy + dz*dz;
        }
        float m01 = fminf(d2[0],d2[1]), m23 = fminf(d2[2],d2[3]);
        float m45 = fminf(d2[4],d2[5]), m67 = fminf(d2[6],d2[7]);
        float mall = fminf(fminf(m01,m23), fminf(m45,m67));
        if (mall < cutoff2) {
            int j   = jbase + i;
            int bj  = j >> 5;
            int ajA = j & 31;
            bool same = (bj == b);
            bool okI  = (s_sepok[bj] != 0);
            float vol = s_vol[i];
            #pragma unroll
            for (int k = 0; k < NPOL_; k++) {
                if (d2[k] < cutoff2) {
                    bool ok = same ? (((s_pmask[k] >> ajA) & 1u) != 0u) : okI;
                    if (ok) {
                        float4 w0 = s_w0[k];
                        float4 w1 = s_w1[k];
                        float d2c = fmaxf(d2[k], 0.01f);
                        float d   = sqrtf(d2c);
                        float xq  = (d - pri[k] - aj.w) * w1.w;
                        float lk  = __fdividef(w0.w * vol * __expf(-xq*xq), d2c);
                        float a0x=w0.x-aj.x, a0y=w0.y-aj.y, a0z=w0.z-aj.z;
                        float dw0 = a0x*a0x + a0y*a0y + a0z*a0z;
                        float a1x=w1.x-aj.x, a1y=w1.y-aj.y, a1z=w1.z-aj.z;
                        float dw1 = a1x*a1x + a1y*a1y + a1z*a1z;
                        float dm = fminf(dw0, dw1);
                        float wt = __saturatef((d2lr - dm) * invramp);
                        float fr = wt*wt*(3.f - 2.f*wt);
                        sum0 += lk;
                        sum1 += lk*fr;
                    }
                }
            }
        }
    }

    // deterministic CTA reduction (fp64)
    double d0 = sum0, d1 = sum1;
    for (int off = 16; off; off >>= 1) {
        d0 += __shfl_xor_sync(FULLM, d0, off);
        d1 += __shfl_xor_sync(FULLM, d1, off);
    }
    int warp = tid >> 5;
    int lane = tid & 31;
    if (lane == 0) { s_red[warp][0]=d0; s_red[warp][1]=d1; }
    __syncthreads();
    if (tid == 0) {
        double a=0, cc=0;
        #pragma unroll
        for (int w = 0; w < TPB_/32; w++) { a+=s_red[w][0]; cc+=s_red[w][1]; }
        g_partial[cta*2]   = a;
        g_partial[cta*2+1] = cc;
    }

    // ---- last-CTA final reduce (fixed-order -> deterministic) ----
    __shared__ bool s_last;
    __threadfence();
    if (tid == 0)
        s_last = (atomicAdd(&g_done, 1u) == (unsigned)(gridDim.x - 1));
    __syncthreads();
    if (!s_last) return;

    __shared__ double rr0[TPB_], rr1[TPB_];
    for (int pp = 0; pp < P_; pp++) {
        double a = 0, cc = 0;
        for (int i = tid; i < B_*CH_; i += TPB_) {
            a  += g_partial[(pp*B_*CH_+i)*2];
            cc += g_partial[(pp*B_*CH_+i)*2+1];
        }
        rr0[tid] = a; rr1[tid] = cc;
        __syncthreads();
        for (int s = TPB_/2; s >= 1; s >>= 1) {
            if (tid < s) { rr0[tid] += rr0[tid+s]; rr1[tid] += rr1[tid+s]; }
            __syncthreads();
        }
        if (tid == 0) {
            out[pp]     = (float)rr0[0];
            out[P_+pp]  = (float)rr1[0];
        }
        __syncthreads();
    }
    if (tid == 0) g_done = 0;            // reset for next graph replay
}

extern "C" void kernel_launch(void* const* d_in, const int* in_sizes, int n_in,
                              void* d_out, int out_size) {
    const float* coords  = (const float*)d_in[0];
    const int*   btype   = (const int*)  d_in[1];
    const int*   minsep  = (const int*)  d_in[2];
    // d_in[3] = bt_n_atoms (unused: all blocks have A_ atoms)
    const int*   bonds   = (const int*)  d_in[4];
    const int*   ranges  = (const int*)  d_in[5];
    const int*   n_donH  = (const int*)  d_in[6];
    const int*   n_acc   = (const int*)  d_in[7];
    const int*   donH_i  = (const int*)  d_in[8];
    const int*   don_hvy = (const int*)  d_in[9];
    const int*   acc_i   = (const int*)  d_in[10];
    const int*   hyb     = (const int*)  d_in[11];
    const int*   is_h    = (const int*)  d_in[12];
    const float* lkp     = (const float*)d_in[13];
    const int*   pathd   = (const int*)  d_in[14];
    const float* lkgp    = (const float*)d_in[15];
    const float* wgp     = (const float*)d_in[16];
    const float* sp2     = (const float*)d_in[17];
    const float* sp3     = (const float*)d_in[18];
    const float* ringt   = (const float*)d_in[19];

    lkball_kernel<<<P_*B_*CH_, TPB_>>>(coords, btype, minsep, bonds, ranges,
                                       n_donH, n_acc, donH_i, don_hvy, acc_i, hyb,
                                       lkp, is_h, pathd, lkgp, wgp, sp2, sp3, ringt,
                                       (float*)d_out);
}

// round 9
// speedup vs baseline: 1.5151x; 1.4286x over previous
#include <cuda_runtime.h>

#define P_ 2
#define B_ 96
#define A_ 32
#define N_ 3072        // B_*A_
#define NT_ 24
#define MD_ 4
#define MA_ 4
#define NPOL_ 8
#define CH_ 3          // j-range chunks per (pose,block)
#define TPB_ 256
#define NW_ (TPB_/32)
#define JCHUNK_ (N_/CH_)       // 1024 j atoms per CTA
#define JPT_ (JCHUNK_/TPB_)    // 4 atoms per thread
#define C_LK 0.0897935610625833f
#define FULLM 0xffffffffu

// Scratch (no allocations allowed)
__device__ double g_partial[P_*B_*CH_*2];
__device__ unsigned int g_done;   // zero-init; last CTA resets -> graph-replay safe

__device__ __forceinline__ int clampA(int v){ return min(max(v,0), A_-1); }

__global__ void __launch_bounds__(TPB_, 4) lkball_kernel(
    const float* __restrict__ coords,
    const int*   __restrict__ btype,
    const int*   __restrict__ minsep,
    const int*   __restrict__ bonds,     // (NT,A,2)
    const int*   __restrict__ ranges,    // (NT,A,2)
    const int*   __restrict__ n_donH,
    const int*   __restrict__ n_acc,
    const int*   __restrict__ donH_i,
    const int*   __restrict__ don_hvy_i,
    const int*   __restrict__ acc_i_arr,
    const int*   __restrict__ hyb_arr,
    const float* __restrict__ lkp,       // (NT,A,4) -> float4 aligned
    const int*   __restrict__ is_h,      // (NT,A)
    const int*   __restrict__ pathd,     // (NT,A,A)
    const float* __restrict__ lkgp,
    const float* __restrict__ wgp,
    const float* __restrict__ sp2t,
    const float* __restrict__ sp3t,
    const float* __restrict__ ringt,
    float*       __restrict__ out)
{
    __shared__ float4 st_pol[NPOL_], st_w0[NPOL_], st_w1[NPOL_];
    __shared__ int    st_a[NPOL_], st_act[NPOL_];
    __shared__ float4 s_pol[NPOL_], s_w0[NPOL_], s_w1[NPOL_];
    __shared__ int    s_arow[NPOL_];
    __shared__ unsigned s_pmask[NPOL_];     // same-block sep>=4 bit per atom-in-block
    __shared__ unsigned char s_sepok[B_];
    __shared__ short  s_bt[B_];
    __shared__ float4 s_xyz[JCHUNK_];       // staged j atoms: x,y,z,rj (H -> -1e6 sentinel)
    __shared__ float  s_vol[JCHUNK_];
    __shared__ double s_red[NW_][2];

    int cta = blockIdx.x;
    int c   = cta % CH_;
    int pb  = cta / CH_;
    int p   = pb / B_;
    int b   = pb - p*B_;
    int tid = threadIdx.x;
    int bt  = btype[p*B_+b];
    const float* cblk = coords + (size_t)(p*N_ + b*A_)*3;
    const float4* lkp4 = (const float4*)lkp;

    // ---- water generation for the 8 polar slots (threads 0..7) ----
    if (tid < NPOL_) {
        float wdist = wgp[0], wang = wgp[1];
        int active = 0, ai = 0;
        float xp0=0,xp1=0,xp2=0,w00=0,w01=0,w02=0,w10=0,w11=0,w12=0;
        if (tid < MD_) {                       // donor slot
            int i = tid;
            if (i < n_donH[bt]) {
                active = 1;
                ai      = clampA(don_hvy_i[bt*MD_+i]);
                int hi  = clampA(donH_i[bt*MD_+i]);
                float hx=cblk[ai*3], hy=cblk[ai*3+1], hz=cblk[ai*3+2];
                float Hx=cblk[hi*3], Hy=cblk[hi*3+1], Hz=cblk[hi*3+2];
                float dx=Hx-hx, dy=Hy-hy, dz=Hz-hz;
                float inv = rsqrtf(dx*dx+dy*dy+dz*dz + 1e-12f);
                xp0=hx; xp1=hy; xp2=hz;
                w00=hx+wdist*inv*dx; w01=hy+wdist*inv*dy; w02=hz+wdist*inv*dz;
                w10=1e5f; w11=1e5f; w12=1e5f;      // masked water -> far sentinel
            }
        } else {                               // acceptor slot
            int i = tid - MD_;
            if (i < n_acc[bt]) {
                active = 1;
                ai        = clampA(acc_i_arr[bt*MA_+i]);
                int r0    = clampA(ranges[(bt*A_+ai)*2]);
                int base  = clampA(bonds [(bt*A_+r0)*2+1]);
                int r1    = clampA(ranges[(bt*A_+base)*2]);
                int base2 = clampA(bonds [(bt*A_+r1)*2+1]);
                float cx=cblk[ai*3],   cy=cblk[ai*3+1],   cz=cblk[ai*3+2];
                float bx=cblk[base*3], by=cblk[base*3+1], bz=cblk[base*3+2];
                float ax=cblk[base2*3],ay=cblk[base2*3+1],az=cblk[base2*3+2];
                float e1x=cx-bx, e1y=cy-by, e1z=cz-bz;
                float inv = rsqrtf(e1x*e1x+e1y*e1y+e1z*e1z + 1e-12f);
                e1x*=inv; e1y*=inv; e1z*=inv;
                float ux=bx-ax, uy=by-ay, uz=bz-az;
                float nx=uy*e1z-uz*e1y, ny=uz*e1x-ux*e1z, nz=ux*e1y-uy*e1x;
                inv = rsqrtf(nx*nx+ny*ny+nz*nz + 1e-12f);
                nx*=inv; ny*=inv; nz*=inv;
                float e2x=ny*e1z-nz*e1y, e2y=nz*e1x-nx*e1z, e2z=nx*e1y-ny*e1x;
                int hyb = hyb_arr[bt*MA_+i];
                float chi0, chi1;
                if      (hyb == 0) { chi0=sp2t[0];  chi1=sp2t[1];  }
                else if (hyb == 1) { chi0=sp3t[0];  chi1=sp3t[1];  }
                else               { chi0=ringt[0]; chi1=ringt[1]; }
                float ct=cosf(wang), st=sinf(wang);
                float a1 = -wdist*ct;
                float b0 = wdist*st*cosf(chi0), c0 = wdist*st*sinf(chi0);
                float b1 = wdist*st*cosf(chi1), c1 = wdist*st*sinf(chi1);
                xp0=cx; xp1=cy; xp2=cz;
                w00 = cx + a1*e1x + b0*e2x + c0*nx;
                w01 = cy + a1*e1y + b0*e2y + c0*ny;
                w02 = cz + a1*e1z + b0*e2z + c0*nz;
                w10 = cx + a1*e1x + b1*e2x + c1*nx;
                w11 = cy + a1*e1y + b1*e2y + c1*ny;
                w12 = cz + a1*e1z + b1*e2z + c1*nz;
            }
        }
        st_act[tid] = active;
        if (active) {
            float4 q = lkp4[bt*A_+ai];           // ri,dgi,lam,vol
            st_pol[tid] = make_float4(xp0, xp1, xp2, q.x);
            st_w0[tid]  = make_float4(w00, w01, w02, C_LK*q.y/q.z);
            st_w1[tid]  = make_float4(w10, w11, w12, 1.0f/q.z);
            st_a[tid]   = ai*A_;
        }
    }
    // inter-block sep mask + block types for this pose
    if (tid < B_) {
        s_sepok[tid] = (minsep[(p*B_+b)*B_+tid] >= 4) ? 1 : 0;
        s_bt[tid]    = (short)btype[p*B_+tid];
    }
    __syncthreads();
    if (tid == 0) {                         // compact + pad to 8 with dummies
        int n = 0;
        for (int t = 0; t < NPOL_; t++) if (st_act[t]) {
            s_pol[n]=st_pol[t]; s_w0[n]=st_w0[t]; s_w1[n]=st_w1[t]; s_arow[n]=st_a[t];
            n++;
        }
        for (; n < NPOL_; n++) {
            s_pol[n]=make_float4(1e6f,1e6f,1e6f,0.f);   // never passes cutoff
            s_w0[n]=make_float4(0,0,0,0); s_w1[n]=make_float4(0,0,0,1.f);
            s_arow[n]=0;
        }
    }
    // stage this CTA's j range: coords+rj (H -> far sentinel), vol
    {
        int jb = c*JCHUNK_;
        const float* cp = coords + (size_t)p*N_*3;
        for (int i = tid; i < JCHUNK_; i += TPB_) {
            int j   = jb + i;
            int bj  = j >> 5;
            int a   = j & 31;
            int btj = s_bt[bj];
            float4 q = lkp4[btj*A_+a];
            bool hyd = (is_h[btj*A_+a] != 0);
            float x = cp[3*j], y = cp[3*j+1], z = cp[3*j+2];
            s_xyz[i] = hyd ? make_float4(-1e6f,-1e6f,-1e6f,0.f)
                           : make_float4(x, y, z, q.x);
            s_vol[i] = q.w;
        }
    }
    __syncthreads();
    // same-block separation bitmasks: warp k -> pol k, lane a -> atom a
    if (tid < NPOL_*32) {
        int k = tid >> 5, a = tid & 31;
        unsigned mk = __ballot_sync(FULLM, pathd[bt*A_*A_ + s_arow[k] + a] >= 4);
        if (a == 0) s_pmask[k] = mk;
    }
    __syncthreads();

    // hoist the 8 polar positions into registers (static indexing only)
    float px[NPOL_], py[NPOL_], pz[NPOL_];
    #pragma unroll
    for (int k = 0; k < NPOL_; k++) {
        float4 q = s_pol[k];
        px[k]=q.x; py[k]=q.y; pz[k]=q.z;
    }

    float cutoff2 = lkgp[0]*lkgp[0];
    float ramp2   = lkgp[1];
    float d2lr    = lkgp[2] + ramp2;
    float invramp = 1.0f/ramp2;

    int jbase = c*JCHUNK_;
    int warp  = tid >> 5;
    int lane  = tid & 31;

    float sum0 = 0.f, sum1 = 0.f;
    #pragma unroll
    for (int it = 0; it < JPT_; it++) {
        int i = it*TPB_ + tid;
        float4 aj = s_xyz[i];               // LDS.128 (H -> far sentinel)
        // build per-lane 8-bit pass mask (no divergence)
        unsigned bits = 0;
        #pragma unroll
        for (int k = 0; k < NPOL_; k++) {
            float dx = px[k]-aj.x, dy = py[k]-aj.y, dz = pz[k]-aj.z;
            float d2 = dx*dx + dy*dy + dz*dz;
            bits |= (d2 < cutoff2) ? (1u << k) : 0u;
        }
        if (bits) {                          // single divergent region
            int j   = jbase + i;
            int bj  = j >> 5;
            int ajA = j & 31;
            bool same = (bj == b);
            float okI = (s_sepok[bj] != 0) ? 1.f : 0.f;
            float vol = s_vol[i];
            do {                             // ~1-2 iterations per lane
                int k = __ffs(bits) - 1;
                bits &= bits - 1u;
                float4 pol = s_pol[k];       // LDS broadcast-ish
                float4 w0  = s_w0[k];
                float4 w1  = s_w1[k];
                float g = same ? (float)((s_pmask[k] >> ajA) & 1u) : okI;
                float dx = pol.x-aj.x, dy = pol.y-aj.y, dz = pol.z-aj.z;
                float d2c = fmaxf(dx*dx + dy*dy + dz*dz, 0.01f);
                float d   = sqrtf(d2c);
                float xq  = (d - pol.w - aj.w) * w1.w;
                float lk  = g * __fdividef(w0.w * vol * __expf(-xq*xq), d2c);
                float a0x=w0.x-aj.x, a0y=w0.y-aj.y, a0z=w0.z-aj.z;
                float dw0 = a0x*a0x + a0y*a0y + a0z*a0z;
                float a1x=w1.x-aj.x, a1y=w1.y-aj.y, a1z=w1.z-aj.z;
                float dw1 = a1x*a1x + a1y*a1y + a1z*a1z;
                float dm = fminf(dw0, dw1);
                float wt = __saturatef((d2lr - dm) * invramp);
                float fr = wt*wt*(3.f - 2.f*wt);
                sum0 += lk;
                sum1 += lk*fr;
            } while (bits);
        }
    }

    // deterministic CTA reduction (fp64)
    double d0 = sum0, d1 = sum1;
    for (int off = 16; off; off >>= 1) {
        d0 += __shfl_xor_sync(FULLM, d0, off);
        d1 += __shfl_xor_sync(FULLM, d1, off);
    }
    if (lane == 0) { s_red[warp][0]=d0; s_red[warp][1]=d1; }
    __syncthreads();
    if (tid == 0) {
        double a=0, cc=0;
        #pragma unroll
        for (int w = 0; w < NW_; w++) { a+=s_red[w][0]; cc+=s_red[w][1]; }
        g_partial[cta*2]   = a;
        g_partial[cta*2+1] = cc;
    }

    // ---- last-CTA final reduce (fixed-order -> deterministic) ----
    __shared__ bool s_last;
    __threadfence();
    if (tid == 0)
        s_last = (atomicAdd(&g_done, 1u) == (unsigned)(gridDim.x - 1));
    __syncthreads();
    if (!s_last) return;

    __shared__ double rr0[TPB_], rr1[TPB_];
    for (int pp = 0; pp < P_; pp++) {
        double a = 0, cc = 0;
        for (int i = tid; i < B_*CH_; i += TPB_) {
            a  += g_partial[(pp*B_*CH_+i)*2];
            cc += g_partial[(pp*B_*CH_+i)*2+1];
        }
        rr0[tid] = a; rr1[tid] = cc;
        __syncthreads();
        for (int s = TPB_/2; s >= 1; s >>= 1) {
            if (tid < s) { rr0[tid] += rr0[tid+s]; rr1[tid] += rr1[tid+s]; }
            __syncthreads();
        }
        if (tid == 0) {
            out[pp]     = (float)rr0[0];
            out[P_+pp]  = (float)rr1[0];
        }
        __syncthreads();
    }
    if (tid == 0) g_done = 0;            // reset for next graph replay
}

extern "C" void kernel_launch(void* const* d_in, const int* in_sizes, int n_in,
                              void* d_out, int out_size) {
    const float* coords  = (const float*)d_in[0];
    const int*   btype   = (const int*)  d_in[1];
    const int*   minsep  = (const int*)  d_in[2];
    // d_in[3] = bt_n_atoms (unused: all blocks have A_ atoms)
    const int*   bonds   = (const int*)  d_in[4];
    const int*   ranges  = (const int*)  d_in[5];
    const int*   n_donH  = (const int*)  d_in[6];
    const int*   n_acc   = (const int*)  d_in[7];
    const int*   donH_i  = (const int*)  d_in[8];
    const int*   don_hvy = (const int*)  d_in[9];
    const int*   acc_i   = (const int*)  d_in[10];
    const int*   hyb     = (const int*)  d_in[11];
    const int*   is_h    = (const int*)  d_in[12];
    const float* lkp     = (const float*)d_in[13];
    const int*   pathd   = (const int*)  d_in[14];
    const float* lkgp    = (const float*)d_in[15];
    const float* wgp     = (const float*)d_in[16];
    const float* sp2     = (const float*)d_in[17];
    const float* sp3     = (const float*)d_in[18];
    const float* ringt   = (const float*)d_in[19];

    lkball_kernel<<<P_*B_*CH_, TPB_>>>(coords, btype, minsep, bonds, ranges,
                                       n_donH, n_acc, donH_i, don_hvy, acc_i, hyb,
                                       lkp, is_h, pathd, lkgp, wgp, sp2, sp3, ringt,
                                       (float*)d_out);
}

// round 10
// speedup vs baseline: 1.6637x; 1.0980x over previous
#include <cuda_runtime.h>

#define P_ 2
#define B_ 96
#define A_ 32
#define N_ 3072        // B_*A_
#define NT_ 24
#define MD_ 4
#define MA_ 4
#define NPOL_ 8
#define CH_ 3          // j-range chunks per (pose,block)
#define TPB_ 256
#define NW_ (TPB_/32)
#define JCHUNK_ (N_/CH_)       // 1024 j atoms per CTA
#define JPT_ (JCHUNK_/TPB_)    // 4 atoms per thread
#define STG_ 224               // staging threads (warps 0-6)
#define C_LK 0.0897935610625833f
#define FULLM 0xffffffffu

// Scratch (no allocations allowed)
__device__ double g_partial[P_*B_*CH_*2];
__device__ unsigned int g_done;   // zero-init; last CTA resets -> graph-replay safe

__device__ __forceinline__ int clampA(int v){ return min(max(v,0), A_-1); }

__global__ void __launch_bounds__(TPB_, 4) lkball_kernel(
    const float* __restrict__ coords,
    const int*   __restrict__ btype,
    const int*   __restrict__ minsep,
    const int*   __restrict__ bonds,     // (NT,A,2)
    const int*   __restrict__ ranges,    // (NT,A,2)
    const int*   __restrict__ n_donH,
    const int*   __restrict__ n_acc,
    const int*   __restrict__ donH_i,
    const int*   __restrict__ don_hvy_i,
    const int*   __restrict__ acc_i_arr,
    const int*   __restrict__ hyb_arr,
    const float* __restrict__ lkp,       // (NT,A,4) -> float4 aligned
    const int*   __restrict__ is_h,      // (NT,A)
    const int*   __restrict__ pathd,     // (NT,A,A)
    const float* __restrict__ lkgp,
    const float* __restrict__ wgp,
    const float* __restrict__ sp2t,
    const float* __restrict__ sp3t,
    const float* __restrict__ ringt,
    float*       __restrict__ out)
{
    __shared__ float4 st_pol[NPOL_], st_w0[NPOL_], st_w1[NPOL_];
    __shared__ int    st_a[NPOL_], st_act[NPOL_];
    __shared__ float4 s_pol[NPOL_], s_w0[NPOL_], s_w1[NPOL_];
    __shared__ int    s_arow[NPOL_];
    __shared__ unsigned s_pmask[NPOL_];     // same-block sep>=4 bit per atom-in-block
    __shared__ unsigned char s_sepok[B_];
    __shared__ short  s_bt[B_];
    __shared__ int    s_rng0[A_], s_b1[A_]; // this block-type's ranges[...,0], bonds[...,1]
    __shared__ float  s_cb[A_*3];           // this block's coords
    __shared__ float4 s_xyz[JCHUNK_];       // staged j atoms: x,y,z,rj (H -> -1e6 sentinel)
    __shared__ float  s_vol[JCHUNK_];
    __shared__ double s_red[NW_][2];

    int cta = blockIdx.x;
    int c   = cta % CH_;
    int pb  = cta / CH_;
    int p   = pb / B_;
    int b   = pb - p*B_;
    int tid = threadIdx.x;
    int bt  = btype[p*B_+b];
    const float* cblk = coords + (size_t)(p*N_ + b*A_)*3;
    const float4* lkp4 = (const float4*)lkp;

    // ---- phase 0: coalesced prefetch of per-block tables (all independent LDGs)
    if (tid < B_) {
        s_sepok[tid] = (minsep[(p*B_+b)*B_+tid] >= 4) ? 1 : 0;
        s_bt[tid]    = (short)btype[p*B_+tid];
    }
    if (tid < A_) {
        s_rng0[tid] = ranges[(bt*A_+tid)*2];
        s_b1[tid]   = bonds [(bt*A_+tid)*2+1];
    }
    if (tid >= 128 && tid < 128 + A_*3) {
        s_cb[tid-128] = cblk[tid-128];
    }
    __syncthreads();

    // ---- phase 1: warp 7 does water generation (smem-fed, short chain)
    //               warps 0-6 stage the j range concurrently
    if (tid >= STG_) {
        int slot = tid - STG_;
        if (slot < NPOL_) {
            float wdist = wgp[0], wang = wgp[1];
            int active = 0, ai = 0;
            float xp0=0,xp1=0,xp2=0,w00=0,w01=0,w02=0,w10=0,w11=0,w12=0;
            if (slot < MD_) {                      // donor slot
                if (slot < n_donH[bt]) {
                    active = 1;
                    ai      = clampA(don_hvy_i[bt*MD_+slot]);
                    int hi  = clampA(donH_i[bt*MD_+slot]);
                    float hx=s_cb[ai*3], hy=s_cb[ai*3+1], hz=s_cb[ai*3+2];
                    float Hx=s_cb[hi*3], Hy=s_cb[hi*3+1], Hz=s_cb[hi*3+2];
                    float dx=Hx-hx, dy=Hy-hy, dz=Hz-hz;
                    float inv = rsqrtf(dx*dx+dy*dy+dz*dz + 1e-12f);
                    xp0=hx; xp1=hy; xp2=hz;
                    w00=hx+wdist*inv*dx; w01=hy+wdist*inv*dy; w02=hz+wdist*inv*dz;
                    w10=1e5f; w11=1e5f; w12=1e5f;  // masked water -> far sentinel
                }
            } else {                               // acceptor slot
                int i = slot - MD_;
                if (i < n_acc[bt]) {
                    active = 1;
                    ai        = clampA(acc_i_arr[bt*MA_+i]);
                    int r0    = clampA(s_rng0[ai]);
                    int base  = clampA(s_b1[r0]);
                    int r1    = clampA(s_rng0[base]);
                    int base2 = clampA(s_b1[r1]);
                    float cx=s_cb[ai*3],   cy=s_cb[ai*3+1],   cz=s_cb[ai*3+2];
                    float bx=s_cb[base*3], by=s_cb[base*3+1], bz=s_cb[base*3+2];
                    float ax=s_cb[base2*3],ay=s_cb[base2*3+1],az=s_cb[base2*3+2];
                    float e1x=cx-bx, e1y=cy-by, e1z=cz-bz;
                    float inv = rsqrtf(e1x*e1x+e1y*e1y+e1z*e1z + 1e-12f);
                    e1x*=inv; e1y*=inv; e1z*=inv;
                    float ux=bx-ax, uy=by-ay, uz=bz-az;
                    float nx=uy*e1z-uz*e1y, ny=uz*e1x-ux*e1z, nz=ux*e1y-uy*e1x;
                    inv = rsqrtf(nx*nx+ny*ny+nz*nz + 1e-12f);
                    nx*=inv; ny*=inv; nz*=inv;
                    float e2x=ny*e1z-nz*e1y, e2y=nz*e1x-nx*e1z, e2z=nx*e1y-ny*e1x;
                    int hyb = hyb_arr[bt*MA_+i];
                    float chi0, chi1;
                    if      (hyb == 0) { chi0=sp2t[0];  chi1=sp2t[1];  }
                    else if (hyb == 1) { chi0=sp3t[0];  chi1=sp3t[1];  }
                    else               { chi0=ringt[0]; chi1=ringt[1]; }
                    float ct=cosf(wang), st=sinf(wang);
                    float a1 = -wdist*ct;
                    float b0 = wdist*st*cosf(chi0), c0 = wdist*st*sinf(chi0);
                    float b1 = wdist*st*cosf(chi1), c1 = wdist*st*sinf(chi1);
                    xp0=cx; xp1=cy; xp2=cz;
                    w00 = cx + a1*e1x + b0*e2x + c0*nx;
                    w01 = cy + a1*e1y + b0*e2y + c0*ny;
                    w02 = cz + a1*e1z + b0*e2z + c0*nz;
                    w10 = cx + a1*e1x + b1*e2x + c1*nx;
                    w11 = cy + a1*e1y + b1*e2y + c1*ny;
                    w12 = cz + a1*e1z + b1*e2z + c1*nz;
                }
            }
            st_act[slot] = active;
            if (active) {
                float4 q = lkp4[bt*A_+ai];         // ri,dgi,lam,vol
                st_pol[slot] = make_float4(xp0, xp1, xp2, q.x);
                st_w0[slot]  = make_float4(w00, w01, w02, C_LK*q.y/q.z);
                st_w1[slot]  = make_float4(w10, w11, w12, 1.0f/q.z);
                st_a[slot]   = ai*A_;
            }
        }
    } else {
        // stage this CTA's j range: coords+rj (H -> far sentinel), vol
        int jb = c*JCHUNK_;
        const float* cp = coords + (size_t)p*N_*3;
        for (int i = tid; i < JCHUNK_; i += STG_) {
            int j   = jb + i;
            int bj  = j >> 5;
            int a   = j & 31;
            int btj = s_bt[bj];
            float4 q = lkp4[btj*A_+a];
            bool hyd = (is_h[btj*A_+a] != 0);
            float x = cp[3*j], y = cp[3*j+1], z = cp[3*j+2];
            s_xyz[i] = hyd ? make_float4(-1e6f,-1e6f,-1e6f,0.f)
                           : make_float4(x, y, z, q.x);
            s_vol[i] = q.w;
        }
    }
    __syncthreads();
    if (tid == 0) {                         // compact + pad to 8 with dummies
        int n = 0;
        for (int t = 0; t < NPOL_; t++) if (st_act[t]) {
            s_pol[n]=st_pol[t]; s_w0[n]=st_w0[t]; s_w1[n]=st_w1[t]; s_arow[n]=st_a[t];
            n++;
        }
        for (; n < NPOL_; n++) {
            s_pol[n]=make_float4(1e6f,1e6f,1e6f,0.f);   // never passes cutoff
            s_w0[n]=make_float4(0,0,0,0); s_w1[n]=make_float4(0,0,0,1.f);
            s_arow[n]=0;
        }
    }
    __syncthreads();
    // same-block separation bitmasks: warp k -> pol k, lane a -> atom a
    if (tid < NPOL_*32) {
        int k = tid >> 5, a = tid & 31;
        unsigned mk = __ballot_sync(FULLM, pathd[bt*A_*A_ + s_arow[k] + a] >= 4);
        if (a == 0) s_pmask[k] = mk;
    }
    __syncthreads();

    // hoist the 8 polar positions into registers (static indexing only)
    float px[NPOL_], py[NPOL_], pz[NPOL_];
    #pragma unroll
    for (int k = 0; k < NPOL_; k++) {
        float4 q = s_pol[k];
        px[k]=q.x; py[k]=q.y; pz[k]=q.z;
    }

    float cutoff2 = lkgp[0]*lkgp[0];
    float ramp2   = lkgp[1];
    float d2lr    = lkgp[2] + ramp2;
    float invramp = 1.0f/ramp2;

    int jbase = c*JCHUNK_;
    int warp  = tid >> 5;
    int lane  = tid & 31;

    float sum0 = 0.f, sum1 = 0.f;
    #pragma unroll
    for (int it = 0; it < JPT_; it += 2) {
        int i0 = it*TPB_ + tid;
        int i1 = i0 + TPB_;
        float4 a0 = s_xyz[i0];              // two independent LDS.128
        float4 a1 = s_xyz[i1];
        unsigned bits0 = 0, bits1 = 0;      // interleaved -> double ILP
        #pragma unroll
        for (int k = 0; k < NPOL_; k++) {
            float dx0 = px[k]-a0.x, dy0 = py[k]-a0.y, dz0 = pz[k]-a0.z;
            float dx1 = px[k]-a1.x, dy1 = py[k]-a1.y, dz1 = pz[k]-a1.z;
            float q0 = dx0*dx0 + dy0*dy0 + dz0*dz0;
            float q1 = dx1*dx1 + dy1*dy1 + dz1*dz1;
            bits0 |= (q0 < cutoff2) ? (1u << k) : 0u;
            bits1 |= (q1 < cutoff2) ? (1u << k) : 0u;
        }
        #pragma unroll
        for (int half = 0; half < 2; half++) {
            unsigned bits = half ? bits1 : bits0;
            float4  aj    = half ? a1 : a0;
            int     i     = half ? i1 : i0;
            if (bits) {                      // single divergent region per atom
                int j   = jbase + i;
                int bj  = j >> 5;
                int ajA = j & 31;
                bool same = (bj == b);
                float okI = (s_sepok[bj] != 0) ? 1.f : 0.f;
                float vol = s_vol[i];
                do {                         // ~1-2 iterations per lane
                    int k = __ffs(bits) - 1;
                    bits &= bits - 1u;
                    float4 pol = s_pol[k];
                    float4 w0  = s_w0[k];
                    float4 w1  = s_w1[k];
                    float g = same ? (float)((s_pmask[k] >> ajA) & 1u) : okI;
                    float dx = pol.x-aj.x, dy = pol.y-aj.y, dz = pol.z-aj.z;
                    float d2c = fmaxf(dx*dx + dy*dy + dz*dz, 0.01f);
                    float rin = rsqrtf(d2c);            // 1/d
                    float d   = d2c * rin;              // d
                    float xq  = (d - pol.w - aj.w) * w1.w;
                    float lk  = g * (w0.w * vol * __expf(-xq*xq)) * (rin*rin);
                    float a0x=w0.x-aj.x, a0y=w0.y-aj.y, a0z=w0.z-aj.z;
                    float dw0 = a0x*a0x + a0y*a0y + a0z*a0z;
                    float a1x=w1.x-aj.x, a1y=w1.y-aj.y, a1z=w1.z-aj.z;
                    float dw1 = a1x*a1x + a1y*a1y + a1z*a1z;
                    float dm = fminf(dw0, dw1);
                    float wt = __saturatef((d2lr - dm) * invramp);
                    float fr = wt*wt*(3.f - 2.f*wt);
                    sum0 += lk;
                    sum1 += lk*fr;
                } while (bits);
            }
        }
    }

    // deterministic CTA reduction (fp64)
    double d0 = sum0, d1 = sum1;
    for (int off = 16; off; off >>= 1) {
        d0 += __shfl_xor_sync(FULLM, d0, off);
        d1 += __shfl_xor_sync(FULLM, d1, off);
    }
    if (lane == 0) { s_red[warp][0]=d0; s_red[warp][1]=d1; }
    __syncthreads();
    if (tid == 0) {
        double a=0, cc=0;
        #pragma unroll
        for (int w = 0; w < NW_; w++) { a+=s_red[w][0]; cc+=s_red[w][1]; }
        g_partial[cta*2]   = a;
        g_partial[cta*2+1] = cc;
    }

    // ---- last-CTA final reduce (fixed-order -> deterministic) ----
    __shared__ bool s_last;
    __threadfence();
    if (tid == 0)
        s_last = (atomicAdd(&g_done, 1u) == (unsigned)(gridDim.x - 1));
    __syncthreads();
    if (!s_last) return;

    __shared__ double rr0[TPB_], rr1[TPB_];
    for (int pp = 0; pp < P_; pp++) {
        double a = 0, cc = 0;
        for (int i = tid; i < B_*CH_; i += TPB_) {
            a  += g_partial[(pp*B_*CH_+i)*2];
            cc += g_partial[(pp*B_*CH_+i)*2+1];
        }
        rr0[tid] = a; rr1[tid] = cc;
        __syncthreads();
        for (int s = TPB_/2; s >= 1; s >>= 1) {
            if (tid < s) { rr0[tid] += rr0[tid+s]; rr1[tid] += rr1[tid+s]; }
            __syncthreads();
        }
        if (tid == 0) {
            out[pp]     = (float)rr0[0];
            out[P_+pp]  = (float)rr1[0];
        }
        __syncthreads();
    }
    if (tid == 0) g_done = 0;            // reset for next graph replay
}

extern "C" void kernel_launch(void* const* d_in, const int* in_sizes, int n_in,
                              void* d_out, int out_size) {
    const float* coords  = (const float*)d_in[0];
    const int*   btype   = (const int*)  d_in[1];
    const int*   minsep  = (const int*)  d_in[2];
    // d_in[3] = bt_n_atoms (unused: all blocks have A_ atoms)
    const int*   bonds   = (const int*)  d_in[4];
    const int*   ranges  = (const int*)  d_in[5];
    const int*   n_donH  = (const int*)  d_in[6];
    const int*   n_acc   = (const int*)  d_in[7];
    const int*   donH_i  = (const int*)  d_in[8];
    const int*   don_hvy = (const int*)  d_in[9];
    const int*   acc_i   = (const int*)  d_in[10];
    const int*   hyb     = (const int*)  d_in[11];
    const int*   is_h    = (const int*)  d_in[12];
    const float* lkp     = (const float*)d_in[13];
    const int*   pathd   = (const int*)  d_in[14];
    const float* lkgp    = (const float*)d_in[15];
    const float* wgp     = (const float*)d_in[16];
    const float* sp2     = (const float*)d_in[17];
    const float* sp3     = (const float*)d_in[18];
    const float* ringt   = (const float*)d_in[19];

    lkball_kernel<<<P_*B_*CH_, TPB_>>>(coords, btype, minsep, bonds, ranges,
                                       n_donH, n_acc, donH_i, don_hvy, acc_i, hyb,
                                       lkp, is_h, pathd, lkgp, wgp, sp2, sp3, ringt,
                                       (float*)d_out);
}